// round 5
// baseline (speedup 1.0000x reference)
#include <cuda_runtime.h>
#include <cstdint>

#define BB 16
#define NN 25200
#define NCLS 80
#define STRIDE 85
#define TOPK 1024
#define MAXDET 300
#define CONF_THRES 0.25f
#define IOU_THR 0.45f
#define MAX_WH 7680.0f
#define BND_CAP 2048
#define CROWS 360            // NMS row cache depth in smem

// -------- scratch (device globals, no allocations) --------
__device__ unsigned long long g_keys[BB * NN];
__device__ unsigned char     g_cls[BB * NN];
__device__ float  g_score [BB * TOPK];
__device__ float4 g_box   [BB * TOPK];   // un-offset xyxy
__device__ float4 g_boxoff[BB * TOPK];   // class-offset xyxy
__device__ float  g_clsf  [BB * TOPK];
__device__ unsigned long long g_mask[(size_t)BB * TOPK * 16]; // suppression bitmatrix
__device__ float  g_bmax[BB];
__device__ float  g_bwh [BB];
__device__ int    g_ctr;

// =====================================================================
// Kernel A: block of 256 stages 16 anchors (5440B) via aligned float4,
// then warp-per-anchor score/argmax from smem.
// key = sortable(score)<<32 | ~anchor  (desc value, asc index ties)
// =====================================================================
__global__ void __launch_bounds__(256) score_kernel(const float* __restrict__ in) {
    __shared__ float s[16 * STRIDE];   // 1360 floats
    int group = blockIdx.x;
    int tid = threadIdx.x;
    if (group == 0 && tid == 0) g_ctr = 0;   // reset for fused final (stream-ordered)

    const float4* src = (const float4*)in + (size_t)group * 340;
    float4* dst = (float4*)s;
    {
        int k0 = tid, k1 = tid + 256;
        dst[k0] = src[k0];
        if (k1 < 340) dst[k1] = src[k1];
    }
    __syncthreads();

    int warp = tid >> 5, lane = tid & 31;
    #pragma unroll
    for (int a0 = 0; a0 < 2; a0++) {
        int a = warp + a0 * 8;
        const float* p = s + a * STRIDE;
        float v0 = p[lane];
        float v1 = p[lane + 32];
        float v2 = (lane < STRIDE - 64) ? p[lane + 64] : 0.0f;
        float obj = __shfl_sync(0xffffffffu, v0, 4);

        float best = -1.0f; int bidx = 1 << 30;
        if (lane >= 5) {
            float pr = v0 * obj;
            if (pr > best) { best = pr; bidx = lane - 5; }
        }
        {
            float pr = v1 * obj; int ci = lane + 27;
            if (pr > best) { best = pr; bidx = ci; }
        }
        if (lane < 21) {
            float pr = v2 * obj; int ci = lane + 59;
            if (pr > best) { best = pr; bidx = ci; }
        }
        #pragma unroll
        for (int off = 16; off > 0; off >>= 1) {
            float ov = __shfl_down_sync(0xffffffffu, best, off);
            int   oi = __shfl_down_sync(0xffffffffu, bidx, off);
            if (ov > best || (ov == best && oi < bidx)) { best = ov; bidx = oi; }
        }
        if (lane == 0) {
            int gidx = group * 16 + a;
            bool valid = (obj > CONF_THRES) && (best > CONF_THRES);
            float score = valid ? best : -1.0f;
            unsigned u = __float_as_uint(score);
            u = (u & 0x80000000u) ? ~u : (u | 0x80000000u);
            unsigned anchor = (unsigned)(gidx % NN);
            g_keys[gidx] = ((unsigned long long)u << 32) | (unsigned)(~anchor);
            g_cls[gidx] = (unsigned char)bidx;
        }
    }
}

// =====================================================================
// Kernel B: per-batch exact sorted top-1024 via 12-bit radix select +
// bitonic sorts. 1 block (1024 thr) per batch. Warp-shuffle scan.
// =====================================================================
__global__ void __launch_bounds__(1024) select_kernel(const float* __restrict__ in) {
    int b = blockIdx.x;
    int tid = threadIdx.x;
    int warp = tid >> 5, lane = tid & 31;

    __shared__ unsigned hist[4096];
    __shared__ unsigned sWsum[32];
    __shared__ unsigned long long win[TOPK];
    __shared__ unsigned long long bnd[BND_CAP];
    __shared__ int sT, sNW, sNB;

    const unsigned long long* keys = g_keys + (size_t)b * NN;

    for (int i = tid; i < 4096; i += 1024) hist[i] = 0;
    __syncthreads();
    for (int i = tid; i < NN; i += 1024) {
        unsigned bin = (unsigned)(keys[i] >> 52);
        atomicAdd(&hist[bin], 1u);
    }
    __syncthreads();

    // descending-bin counts; thread t covers rbins 4t..4t+3
    unsigned cnt[4]; unsigned psum = 0;
    #pragma unroll
    for (int k = 0; k < 4; k++) { cnt[k] = hist[4095 - (4 * tid + k)]; psum += cnt[k]; }
    // warp-shuffle exclusive scan over 1024 threads
    unsigned inc = psum;
    #pragma unroll
    for (int o = 1; o < 32; o <<= 1) {
        unsigned t = __shfl_up_sync(0xffffffffu, inc, o);
        if (lane >= o) inc += t;
    }
    if (lane == 31) sWsum[warp] = inc;
    __syncthreads();
    if (warp == 0) {
        unsigned wv = sWsum[lane];
        unsigned wi = wv;
        #pragma unroll
        for (int o = 1; o < 32; o <<= 1) {
            unsigned t = __shfl_up_sync(0xffffffffu, wi, o);
            if (lane >= o) wi += t;
        }
        sWsum[lane] = wi - wv;  // exclusive warp offset
    }
    __syncthreads();
    unsigned before = sWsum[warp] + inc - psum;

    unsigned c = before;
    #pragma unroll
    for (int k = 0; k < 4; k++) {
        unsigned h = cnt[k];
        if (c < TOPK && c + h >= TOPK) sT = 4095 - (4 * tid + k);
        c += h;
    }
    if (tid == 0) { sNW = 0; sNB = 0; }
    __syncthreads();

    int T = sT;
    for (int i = tid; i < NN; i += 1024) {
        unsigned long long k = keys[i];
        int bin = (int)(k >> 52);
        if (bin > T) { int pos = atomicAdd(&sNW, 1); win[pos] = k; }
        else if (bin == T) { int pos = atomicAdd(&sNB, 1); if (pos < BND_CAP) bnd[pos] = k; }
    }
    __syncthreads();
    int nB = sNB < BND_CAP ? sNB : BND_CAP;
    for (int i = tid; i < BND_CAP; i += 1024) if (i >= nB) bnd[i] = 0ULL;
    __syncthreads();

    // bitonic sort bnd (desc), 2048 elems / 1024 threads
    for (int k = 2; k <= BND_CAP; k <<= 1) {
        for (int j = k >> 1; j > 0; j >>= 1) {
            #pragma unroll
            for (int h = 0; h < 2; h++) {
                int i = tid + h * 1024;
                int ixj = i ^ j;
                if (ixj > i) {
                    bool desc = ((i & k) == 0);
                    unsigned long long a = bnd[i], d = bnd[ixj];
                    bool sw = desc ? (a < d) : (a > d);
                    if (sw) { bnd[i] = d; bnd[ixj] = a; }
                }
            }
            __syncthreads();
        }
    }

    int nW = sNW;
    int need = TOPK - nW;
    for (int i = tid; i < need; i += 1024) win[nW + i] = bnd[i];
    __syncthreads();

    // final sort needed only when there are unsorted winners
    if (nW > 0) {
        for (int k = 2; k <= TOPK; k <<= 1) {
            for (int j = k >> 1; j > 0; j >>= 1) {
                int i = tid, ixj = i ^ j;
                if (ixj > i) {
                    bool desc = ((i & k) == 0);
                    unsigned long long a = win[i], d = win[ixj];
                    bool sw = desc ? (a < d) : (a > d);
                    if (sw) { win[i] = d; win[ixj] = a; }
                }
                __syncthreads();
            }
        }
    }

    // decode + emit
    {
        unsigned long long key = win[tid];
        unsigned u = (unsigned)(key >> 32);
        unsigned fb = (u & 0x80000000u) ? (u ^ 0x80000000u) : ~u;
        float score = __uint_as_float(fb);
        unsigned idx = ~((unsigned)(key & 0xffffffffu));

        const float* p = in + ((size_t)b * NN + idx) * STRIDE;
        float cx = p[0], cy = p[1], w = p[2], h = p[3];
        float x1 = cx - w * 0.5f, y1 = cy - h * 0.5f;
        float x2 = cx + w * 0.5f, y2 = cy + h * 0.5f;
        float cf = (float)g_cls[(size_t)b * NN + idx];
        float off = cf * MAX_WH;

        g_score [b * TOPK + tid] = score;
        g_box   [b * TOPK + tid] = make_float4(x1, y1, x2, y2);
        g_boxoff[b * TOPK + tid] = make_float4(x1 + off, y1 + off, x2 + off, y2 + off);
        g_clsf  [b * TOPK + tid] = cf;
    }
}

// =====================================================================
// Kernel C1: parallel suppression bitmatrix.
// mask[b][i][w] bit k set iff j=64w+k > i and iou(i,j) > thr.
// grid (128, BB), block 256: warp per row i, ballots over columns.
// =====================================================================
__global__ void __launch_bounds__(256) iou_kernel() {
    int b = blockIdx.y;
    int tid = threadIdx.x, warp = tid >> 5, lane = tid & 31;
    __shared__ float4 cb[TOPK];
    for (int j = tid; j < TOPK; j += 256) cb[j] = g_boxoff[b * TOPK + j];
    __syncthreads();

    int i = blockIdx.x * 8 + warp;
    float4 bi = cb[i];
    float ai = (bi.z - bi.x) * (bi.w - bi.y);
    unsigned long long myw = 0;
    #pragma unroll 4
    for (int s = 0; s < 32; s++) {
        int j = s * 32 + lane;
        float4 bj = cb[j];
        float lx = fmaxf(bi.x, bj.x);
        float ly = fmaxf(bi.y, bj.y);
        float rx = fminf(bi.z, bj.z);
        float ry = fminf(bi.w, bj.w);
        float iw = fmaxf(rx - lx, 0.0f);
        float ih = fmaxf(ry - ly, 0.0f);
        float inter = iw * ih;
        float aj = (bj.z - bj.x) * (bj.w - bj.y);
        float iou = inter / (ai + aj - inter + 1e-07f);
        bool pred = (j > i) && (iou > IOU_THR);
        unsigned bal = __ballot_sync(0xffffffffu, pred);
        if (lane == (s >> 1)) myw |= ((unsigned long long)bal) << ((s & 1) * 32);
    }
    if (lane < 16) g_mask[((size_t)b * TOPK + i) * 16 + lane] = myw;
}

// =====================================================================
// Kernel C2: single-warp greedy sweep over cached mask rows + stats +
// det[2] output + fused final reduction (last block).
// grid BB, block 512.
// =====================================================================
__global__ void __launch_bounds__(512) nms_kernel(float* __restrict__ out) {
    int b = blockIdx.x, tid = threadIdx.x, warp = tid >> 5, lane = tid & 31;
    __shared__ unsigned long long sRows[CROWS * 16];
    __shared__ unsigned long long sRem[16];
    __shared__ int sKeptIdx[MAXDET];
    __shared__ int sN;
    __shared__ float sRed[16];

    const unsigned long long* mrow = g_mask + (size_t)b * TOPK * 16;
    for (int k = tid; k < CROWS * 16; k += 512) sRows[k] = mrow[k];

    // init removed: 16 warps each build one word via ballots
    {
        float s0 = g_score[b * TOPK + warp * 64 + lane];
        float s1 = g_score[b * TOPK + warp * 64 + 32 + lane];
        unsigned lo = __ballot_sync(0xffffffffu, s0 <= 0.0f);
        unsigned hi = __ballot_sync(0xffffffffu, s1 <= 0.0f);
        if (lane == 0) sRem[warp] = ((unsigned long long)hi << 32) | lo;
    }
    __syncthreads();

    if (warp == 0) {
        unsigned long long rem = (lane < 16) ? sRem[lane] : ~0ULL;
        int kept = 0;
        for (int i = 0; i < TOPK; i++) {
            int w = i >> 6;
            int dead = (int)((rem >> (i & 63)) & 1ULL);
            dead = __shfl_sync(0xffffffffu, dead, w);
            if (!dead) {
                if (lane == 0) sKeptIdx[kept] = i;
                kept++;
                if (kept == MAXDET) break;
                unsigned long long r = 0;
                if (lane < 16) r = (i < CROWS) ? sRows[i * 16 + lane]
                                               : mrow[(size_t)i * 16 + lane];
                rem |= r;
            }
        }
        if (lane == 0) sN = kept;
    }
    __syncthreads();
    int n = sN;

    float contrib = 0.0f;
    float4 bbx = make_float4(0, 0, 0, 0);
    float sc = 0.0f, cf = 0.0f;
    bool emit = (tid < n);
    if (emit) {
        int i = sKeptIdx[tid];
        sc = g_score[b * TOPK + i];
        bbx = g_box[b * TOPK + i];
        cf = g_clsf[b * TOPK + i];
        contrib = (fabsf(bbx.x - bbx.z) + fabsf(bbx.y - bbx.w)) * sc;
    }

    // block sum (16 warps)
    float v = contrib;
    #pragma unroll
    for (int o = 16; o > 0; o >>= 1) v += __shfl_down_sync(0xffffffffu, v, o);
    if (lane == 0) sRed[warp] = v;
    __syncthreads();
    if (tid == 0) {
        float x = 0.0f;
        #pragma unroll
        for (int k = 0; k < 16; k++) x += sRed[k];
        int mx = n > 1 ? n : 1;
        g_bwh[b]  = (n > 0) ? (x / (2.0f * (float)mx)) : 0.0f;
        g_bmax[b] = (n > 0) ? g_score[b * TOPK + sKeptIdx[0]] : 0.0f;
    }

    // det[2] -> out[2 + r*6 ..]
    if (b == 2) {
        if (emit) {
            float* row = out + 2 + tid * 6;
            row[0] = bbx.x; row[1] = bbx.y; row[2] = bbx.z; row[3] = bbx.w;
            row[4] = sc; row[5] = cf;
        }
        if (tid >= n && tid < MAXDET) {
            float* row = out + 2 + tid * 6;
            #pragma unroll
            for (int k = 0; k < 6; k++) row[k] = 0.0f;
        }
    }

    // fused final reduction: last block to finish does the 16-wide sums
    __syncthreads();
    if (tid == 0) {
        __threadfence();
        if (atomicAdd(&g_ctr, 1) == BB - 1) {
            float m = 0.0f, w = 0.0f;
            #pragma unroll
            for (int k = 0; k < BB; k++) {
                m += __ldcg(&g_bmax[k]);
                w += __ldcg(&g_bwh[k]);
            }
            out[0] = m / (float)BB;
            out[1] = w / (float)BB;
        }
    }
}

extern "C" void kernel_launch(void* const* d_in, const int* in_sizes, int n_in,
                              void* d_out, int out_size) {
    const float* in = (const float*)d_in[0];
    float* out = (float*)d_out;

    score_kernel<<<BB * NN / 16, 256>>>(in);   // 25200 blocks
    select_kernel<<<BB, 1024>>>(in);
    iou_kernel<<<dim3(TOPK / 8, BB), 256>>>();
    nms_kernel<<<BB, 512>>>(out);
}

// round 6
// speedup vs baseline: 1.0400x; 1.0400x over previous
#include <cuda_runtime.h>
#include <cstdint>

#define BB 16
#define NN 25200
#define NCLS 80
#define STRIDE 85
#define TOPK 1024
#define MAXDET 300
#define CONF_THRES 0.25f
#define IOU_THR 0.45f
#define MAX_WH 7680.0f
#define BND_CAP 2048
#define CROWS 360            // NMS row cache depth in smem

// -------- scratch (device globals, no allocations) --------
__device__ unsigned long long g_keys[BB * NN];
__device__ unsigned char     g_cls[BB * NN];
__device__ float  g_score [BB * TOPK];
__device__ float4 g_box   [BB * TOPK];   // un-offset xyxy
__device__ float4 g_boxoff[BB * TOPK];   // class-offset xyxy
__device__ float  g_clsf  [BB * TOPK];
__device__ unsigned long long g_mask[(size_t)BB * TOPK * 16]; // suppression bitmatrix
__device__ float  g_bmax[BB];
__device__ float  g_bwh [BB];
__device__ int    g_ctr;

// =====================================================================
// Kernel A: block of 256 stages 16 anchors (5440B) via aligned float4,
// then warp-per-anchor score/argmax from smem.
// key = sortable(score)<<32 | ~anchor  (desc value, asc index ties)
// =====================================================================
__global__ void __launch_bounds__(256) score_kernel(const float* __restrict__ in) {
    __shared__ float s[16 * STRIDE];   // 1360 floats
    int group = blockIdx.x;
    int tid = threadIdx.x;
    if (group == 0 && tid == 0) g_ctr = 0;   // reset for fused final (stream-ordered)

    const float4* src = (const float4*)in + (size_t)group * 340;
    float4* dst = (float4*)s;
    {
        int k0 = tid, k1 = tid + 256;
        dst[k0] = src[k0];
        if (k1 < 340) dst[k1] = src[k1];
    }
    __syncthreads();

    int warp = tid >> 5, lane = tid & 31;
    #pragma unroll
    for (int a0 = 0; a0 < 2; a0++) {
        int a = warp + a0 * 8;
        const float* p = s + a * STRIDE;
        float v0 = p[lane];
        float v1 = p[lane + 32];
        float v2 = (lane < STRIDE - 64) ? p[lane + 64] : 0.0f;
        float obj = __shfl_sync(0xffffffffu, v0, 4);

        float best = -1.0f; int bidx = 1 << 30;
        if (lane >= 5) {
            float pr = v0 * obj;
            if (pr > best) { best = pr; bidx = lane - 5; }
        }
        {
            float pr = v1 * obj; int ci = lane + 27;
            if (pr > best) { best = pr; bidx = ci; }
        }
        if (lane < 21) {
            float pr = v2 * obj; int ci = lane + 59;
            if (pr > best) { best = pr; bidx = ci; }
        }
        #pragma unroll
        for (int off = 16; off > 0; off >>= 1) {
            float ov = __shfl_down_sync(0xffffffffu, best, off);
            int   oi = __shfl_down_sync(0xffffffffu, bidx, off);
            if (ov > best || (ov == best && oi < bidx)) { best = ov; bidx = oi; }
        }
        if (lane == 0) {
            int gidx = group * 16 + a;
            bool valid = (obj > CONF_THRES) && (best > CONF_THRES);
            float score = valid ? best : -1.0f;
            unsigned u = __float_as_uint(score);
            u = (u & 0x80000000u) ? ~u : (u | 0x80000000u);
            unsigned anchor = (unsigned)(gidx % NN);
            g_keys[gidx] = ((unsigned long long)u << 32) | (unsigned)(~anchor);
            g_cls[gidx] = (unsigned char)bidx;
        }
    }
}

// =====================================================================
// Kernel B: per-batch exact sorted top-1024 via 12-bit radix select +
// bitonic sorts. 1 block (1024 thr) per batch. Warp-shuffle scan.
// =====================================================================
__global__ void __launch_bounds__(1024) select_kernel(const float* __restrict__ in) {
    int b = blockIdx.x;
    int tid = threadIdx.x;
    int warp = tid >> 5, lane = tid & 31;

    __shared__ unsigned hist[4096];
    __shared__ unsigned sWsum[32];
    __shared__ unsigned long long win[TOPK];
    __shared__ unsigned long long bnd[BND_CAP];
    __shared__ int sT, sNW, sNB;

    const unsigned long long* keys = g_keys + (size_t)b * NN;

    for (int i = tid; i < 4096; i += 1024) hist[i] = 0;
    __syncthreads();
    for (int i = tid; i < NN; i += 1024) {
        unsigned bin = (unsigned)(keys[i] >> 52);
        atomicAdd(&hist[bin], 1u);
    }
    __syncthreads();

    // descending-bin counts; thread t covers rbins 4t..4t+3
    unsigned cnt[4]; unsigned psum = 0;
    #pragma unroll
    for (int k = 0; k < 4; k++) { cnt[k] = hist[4095 - (4 * tid + k)]; psum += cnt[k]; }
    // warp-shuffle exclusive scan over 1024 threads
    unsigned inc = psum;
    #pragma unroll
    for (int o = 1; o < 32; o <<= 1) {
        unsigned t = __shfl_up_sync(0xffffffffu, inc, o);
        if (lane >= o) inc += t;
    }
    if (lane == 31) sWsum[warp] = inc;
    __syncthreads();
    if (warp == 0) {
        unsigned wv = sWsum[lane];
        unsigned wi = wv;
        #pragma unroll
        for (int o = 1; o < 32; o <<= 1) {
            unsigned t = __shfl_up_sync(0xffffffffu, wi, o);
            if (lane >= o) wi += t;
        }
        sWsum[lane] = wi - wv;  // exclusive warp offset
    }
    __syncthreads();
    unsigned before = sWsum[warp] + inc - psum;

    unsigned c = before;
    #pragma unroll
    for (int k = 0; k < 4; k++) {
        unsigned h = cnt[k];
        if (c < TOPK && c + h >= TOPK) sT = 4095 - (4 * tid + k);
        c += h;
    }
    if (tid == 0) { sNW = 0; sNB = 0; }
    __syncthreads();

    int T = sT;
    for (int i = tid; i < NN; i += 1024) {
        unsigned long long k = keys[i];
        int bin = (int)(k >> 52);
        if (bin > T) { int pos = atomicAdd(&sNW, 1); win[pos] = k; }
        else if (bin == T) { int pos = atomicAdd(&sNB, 1); if (pos < BND_CAP) bnd[pos] = k; }
    }
    __syncthreads();
    int nB = sNB < BND_CAP ? sNB : BND_CAP;
    for (int i = tid; i < BND_CAP; i += 1024) if (i >= nB) bnd[i] = 0ULL;
    __syncthreads();

    // bitonic sort bnd (desc), 2048 elems / 1024 threads
    for (int k = 2; k <= BND_CAP; k <<= 1) {
        for (int j = k >> 1; j > 0; j >>= 1) {
            #pragma unroll
            for (int h = 0; h < 2; h++) {
                int i = tid + h * 1024;
                int ixj = i ^ j;
                if (ixj > i) {
                    bool desc = ((i & k) == 0);
                    unsigned long long a = bnd[i], d = bnd[ixj];
                    bool sw = desc ? (a < d) : (a > d);
                    if (sw) { bnd[i] = d; bnd[ixj] = a; }
                }
            }
            __syncthreads();
        }
    }

    int nW = sNW;
    int need = TOPK - nW;
    for (int i = tid; i < need; i += 1024) win[nW + i] = bnd[i];
    __syncthreads();

    // final sort needed only when there are unsorted winners
    if (nW > 0) {
        for (int k = 2; k <= TOPK; k <<= 1) {
            for (int j = k >> 1; j > 0; j >>= 1) {
                int i = tid, ixj = i ^ j;
                if (ixj > i) {
                    bool desc = ((i & k) == 0);
                    unsigned long long a = win[i], d = win[ixj];
                    bool sw = desc ? (a < d) : (a > d);
                    if (sw) { win[i] = d; win[ixj] = a; }
                }
                __syncthreads();
            }
        }
    }

    // decode + emit
    {
        unsigned long long key = win[tid];
        unsigned u = (unsigned)(key >> 32);
        unsigned fb = (u & 0x80000000u) ? (u ^ 0x80000000u) : ~u;
        float score = __uint_as_float(fb);
        unsigned idx = ~((unsigned)(key & 0xffffffffu));

        const float* p = in + ((size_t)b * NN + idx) * STRIDE;
        float cx = p[0], cy = p[1], w = p[2], h = p[3];
        float x1 = cx - w * 0.5f, y1 = cy - h * 0.5f;
        float x2 = cx + w * 0.5f, y2 = cy + h * 0.5f;
        float cf = (float)g_cls[(size_t)b * NN + idx];
        float off = cf * MAX_WH;

        g_score [b * TOPK + tid] = score;
        g_box   [b * TOPK + tid] = make_float4(x1, y1, x2, y2);
        g_boxoff[b * TOPK + tid] = make_float4(x1 + off, y1 + off, x2 + off, y2 + off);
        g_clsf  [b * TOPK + tid] = cf;
    }
}

// =====================================================================
// Kernel C1: parallel suppression bitmatrix.
// mask[b][i][w] bit k set iff j=64w+k > i and iou(i,j) > thr.
// grid (128, BB), block 256: warp per row i, ballots over columns.
// =====================================================================
__global__ void __launch_bounds__(256) iou_kernel() {
    int b = blockIdx.y;
    int tid = threadIdx.x, warp = tid >> 5, lane = tid & 31;
    __shared__ float4 cb[TOPK];
    for (int j = tid; j < TOPK; j += 256) cb[j] = g_boxoff[b * TOPK + j];
    __syncthreads();

    int i = blockIdx.x * 8 + warp;
    float4 bi = cb[i];
    float ai = (bi.z - bi.x) * (bi.w - bi.y);
    unsigned long long myw = 0;
    #pragma unroll 4
    for (int s = 0; s < 32; s++) {
        int j = s * 32 + lane;
        float4 bj = cb[j];
        float lx = fmaxf(bi.x, bj.x);
        float ly = fmaxf(bi.y, bj.y);
        float rx = fminf(bi.z, bj.z);
        float ry = fminf(bi.w, bj.w);
        float iw = fmaxf(rx - lx, 0.0f);
        float ih = fmaxf(ry - ly, 0.0f);
        float inter = iw * ih;
        float aj = (bj.z - bj.x) * (bj.w - bj.y);
        float iou = inter / (ai + aj - inter + 1e-07f);
        bool pred = (j > i) && (iou > IOU_THR);
        unsigned bal = __ballot_sync(0xffffffffu, pred);
        if (lane == (s >> 1)) myw |= ((unsigned long long)bal) << ((s & 1) * 32);
    }
    if (lane < 16) g_mask[((size_t)b * TOPK + i) * 16 + lane] = myw;
}

// =====================================================================
// Kernel C2: single-warp greedy sweep over cached mask rows + stats +
// det[2] output + fused final reduction (last block).
// grid BB, block 512.
// =====================================================================
__global__ void __launch_bounds__(512) nms_kernel(float* __restrict__ out) {
    int b = blockIdx.x, tid = threadIdx.x, warp = tid >> 5, lane = tid & 31;
    __shared__ unsigned long long sRows[CROWS * 16];
    __shared__ unsigned long long sRem[16];
    __shared__ int sKeptIdx[MAXDET];
    __shared__ int sN;
    __shared__ float sRed[16];

    const unsigned long long* mrow = g_mask + (size_t)b * TOPK * 16;
    for (int k = tid; k < CROWS * 16; k += 512) sRows[k] = mrow[k];

    // init removed: 16 warps each build one word via ballots
    {
        float s0 = g_score[b * TOPK + warp * 64 + lane];
        float s1 = g_score[b * TOPK + warp * 64 + 32 + lane];
        unsigned lo = __ballot_sync(0xffffffffu, s0 <= 0.0f);
        unsigned hi = __ballot_sync(0xffffffffu, s1 <= 0.0f);
        if (lane == 0) sRem[warp] = ((unsigned long long)hi << 32) | lo;
    }
    __syncthreads();

    if (warp == 0) {
        unsigned long long rem = (lane < 16) ? sRem[lane] : ~0ULL;
        int kept = 0;
        for (int i = 0; i < TOPK; i++) {
            int w = i >> 6;
            int dead = (int)((rem >> (i & 63)) & 1ULL);
            dead = __shfl_sync(0xffffffffu, dead, w);
            if (!dead) {
                if (lane == 0) sKeptIdx[kept] = i;
                kept++;
                if (kept == MAXDET) break;
                unsigned long long r = 0;
                if (lane < 16) r = (i < CROWS) ? sRows[i * 16 + lane]
                                               : mrow[(size_t)i * 16 + lane];
                rem |= r;
            }
        }
        if (lane == 0) sN = kept;
    }
    __syncthreads();
    int n = sN;

    float contrib = 0.0f;
    float4 bbx = make_float4(0, 0, 0, 0);
    float sc = 0.0f, cf = 0.0f;
    bool emit = (tid < n);
    if (emit) {
        int i = sKeptIdx[tid];
        sc = g_score[b * TOPK + i];
        bbx = g_box[b * TOPK + i];
        cf = g_clsf[b * TOPK + i];
        contrib = (fabsf(bbx.x - bbx.z) + fabsf(bbx.y - bbx.w)) * sc;
    }

    // block sum (16 warps)
    float v = contrib;
    #pragma unroll
    for (int o = 16; o > 0; o >>= 1) v += __shfl_down_sync(0xffffffffu, v, o);
    if (lane == 0) sRed[warp] = v;
    __syncthreads();
    if (tid == 0) {
        float x = 0.0f;
        #pragma unroll
        for (int k = 0; k < 16; k++) x += sRed[k];
        int mx = n > 1 ? n : 1;
        g_bwh[b]  = (n > 0) ? (x / (2.0f * (float)mx)) : 0.0f;
        g_bmax[b] = (n > 0) ? g_score[b * TOPK + sKeptIdx[0]] : 0.0f;
    }

    // det[2] -> out[2 + r*6 ..]
    if (b == 2) {
        if (emit) {
            float* row = out + 2 + tid * 6;
            row[0] = bbx.x; row[1] = bbx.y; row[2] = bbx.z; row[3] = bbx.w;
            row[4] = sc; row[5] = cf;
        }
        if (tid >= n && tid < MAXDET) {
            float* row = out + 2 + tid * 6;
            #pragma unroll
            for (int k = 0; k < 6; k++) row[k] = 0.0f;
        }
    }

    // fused final reduction: last block to finish does the 16-wide sums
    __syncthreads();
    if (tid == 0) {
        __threadfence();
        if (atomicAdd(&g_ctr, 1) == BB - 1) {
            float m = 0.0f, w = 0.0f;
            #pragma unroll
            for (int k = 0; k < BB; k++) {
                m += __ldcg(&g_bmax[k]);
                w += __ldcg(&g_bwh[k]);
            }
            out[0] = m / (float)BB;
            out[1] = w / (float)BB;
        }
    }
}

extern "C" void kernel_launch(void* const* d_in, const int* in_sizes, int n_in,
                              void* d_out, int out_size) {
    const float* in = (const float*)d_in[0];
    float* out = (float*)d_out;

    score_kernel<<<BB * NN / 16, 256>>>(in);   // 25200 blocks
    select_kernel<<<BB, 1024>>>(in);
    iou_kernel<<<dim3(TOPK / 8, BB), 256>>>();
    nms_kernel<<<BB, 512>>>(out);
}

// round 7
// speedup vs baseline: 1.0963x; 1.0541x over previous
#include <cuda_runtime.h>
#include <cstdint>

#define BB 16
#define NN 25200
#define NCLS 80
#define STRIDE 85
#define TOPK 1024
#define MAXDET 300
#define CONF_THRES 0.25f
#define IOU_THR 0.45f
#define MAX_WH 7680.0f
#define BND_CAP 2048

// -------- scratch (device globals, no allocations) --------
__device__ unsigned long long g_keys[BB * NN];
__device__ unsigned char     g_cls[BB * NN];
__device__ float  g_score [BB * TOPK];
__device__ float4 g_box   [BB * TOPK];   // un-offset xyxy
__device__ float4 g_boxoff[BB * TOPK];   // class-offset xyxy
__device__ float  g_clsf  [BB * TOPK];
__device__ unsigned long long g_mask[(size_t)BB * TOPK * 16]; // suppression bitmatrix
__device__ float  g_bmax[BB];
__device__ float  g_bwh [BB];
__device__ int    g_ctr;

// =====================================================================
// Kernel A: block of 256 stages 16 anchors (5440B) via aligned float4,
// then warp-per-anchor score/argmax from smem.
// key = sortable(score)<<32 | ~anchor  (desc value, asc index ties)
// =====================================================================
__global__ void __launch_bounds__(256) score_kernel(const float* __restrict__ in) {
    __shared__ float s[16 * STRIDE];   // 1360 floats
    int group = blockIdx.x;
    int tid = threadIdx.x;
    if (group == 0 && tid == 0) g_ctr = 0;   // reset for fused final (stream-ordered)

    const float4* src = (const float4*)in + (size_t)group * 340;
    float4* dst = (float4*)s;
    {
        int k0 = tid, k1 = tid + 256;
        dst[k0] = src[k0];
        if (k1 < 340) dst[k1] = src[k1];
    }
    __syncthreads();

    int warp = tid >> 5, lane = tid & 31;
    #pragma unroll
    for (int a0 = 0; a0 < 2; a0++) {
        int a = warp + a0 * 8;
        const float* p = s + a * STRIDE;
        float v0 = p[lane];
        float v1 = p[lane + 32];
        float v2 = (lane < STRIDE - 64) ? p[lane + 64] : 0.0f;
        float obj = __shfl_sync(0xffffffffu, v0, 4);

        float best = -1.0f; int bidx = 1 << 30;
        if (lane >= 5) {
            float pr = v0 * obj;
            if (pr > best) { best = pr; bidx = lane - 5; }
        }
        {
            float pr = v1 * obj; int ci = lane + 27;
            if (pr > best) { best = pr; bidx = ci; }
        }
        if (lane < 21) {
            float pr = v2 * obj; int ci = lane + 59;
            if (pr > best) { best = pr; bidx = ci; }
        }
        #pragma unroll
        for (int off = 16; off > 0; off >>= 1) {
            float ov = __shfl_down_sync(0xffffffffu, best, off);
            int   oi = __shfl_down_sync(0xffffffffu, bidx, off);
            if (ov > best || (ov == best && oi < bidx)) { best = ov; bidx = oi; }
        }
        if (lane == 0) {
            int gidx = group * 16 + a;
            bool valid = (obj > CONF_THRES) && (best > CONF_THRES);
            float score = valid ? best : -1.0f;
            unsigned u = __float_as_uint(score);
            u = (u & 0x80000000u) ? ~u : (u | 0x80000000u);
            unsigned anchor = (unsigned)(gidx % NN);
            g_keys[gidx] = ((unsigned long long)u << 32) | (unsigned)(~anchor);
            g_cls[gidx] = (unsigned char)bidx;
        }
    }
}

// =====================================================================
// Kernel B: per-batch exact sorted top-1024 via 12-bit radix select +
// bitonic sorts. 1 block (1024 thr) per batch. Warp-shuffle scan.
// =====================================================================
__global__ void __launch_bounds__(1024) select_kernel(const float* __restrict__ in) {
    int b = blockIdx.x;
    int tid = threadIdx.x;
    int warp = tid >> 5, lane = tid & 31;

    __shared__ unsigned hist[4096];
    __shared__ unsigned sWsum[32];
    __shared__ unsigned long long win[TOPK];
    __shared__ unsigned long long bnd[BND_CAP];
    __shared__ int sT, sNW, sNB;

    const unsigned long long* keys = g_keys + (size_t)b * NN;

    for (int i = tid; i < 4096; i += 1024) hist[i] = 0;
    __syncthreads();
    for (int i = tid; i < NN; i += 1024) {
        unsigned bin = (unsigned)(keys[i] >> 52);
        atomicAdd(&hist[bin], 1u);
    }
    __syncthreads();

    // descending-bin counts; thread t covers rbins 4t..4t+3
    unsigned cnt[4]; unsigned psum = 0;
    #pragma unroll
    for (int k = 0; k < 4; k++) { cnt[k] = hist[4095 - (4 * tid + k)]; psum += cnt[k]; }
    // warp-shuffle exclusive scan over 1024 threads
    unsigned inc = psum;
    #pragma unroll
    for (int o = 1; o < 32; o <<= 1) {
        unsigned t = __shfl_up_sync(0xffffffffu, inc, o);
        if (lane >= o) inc += t;
    }
    if (lane == 31) sWsum[warp] = inc;
    __syncthreads();
    if (warp == 0) {
        unsigned wv = sWsum[lane];
        unsigned wi = wv;
        #pragma unroll
        for (int o = 1; o < 32; o <<= 1) {
            unsigned t = __shfl_up_sync(0xffffffffu, wi, o);
            if (lane >= o) wi += t;
        }
        sWsum[lane] = wi - wv;  // exclusive warp offset
    }
    __syncthreads();
    unsigned before = sWsum[warp] + inc - psum;

    unsigned c = before;
    #pragma unroll
    for (int k = 0; k < 4; k++) {
        unsigned h = cnt[k];
        if (c < TOPK && c + h >= TOPK) sT = 4095 - (4 * tid + k);
        c += h;
    }
    if (tid == 0) { sNW = 0; sNB = 0; }
    __syncthreads();

    int T = sT;
    for (int i = tid; i < NN; i += 1024) {
        unsigned long long k = keys[i];
        int bin = (int)(k >> 52);
        if (bin > T) { int pos = atomicAdd(&sNW, 1); win[pos] = k; }
        else if (bin == T) { int pos = atomicAdd(&sNB, 1); if (pos < BND_CAP) bnd[pos] = k; }
    }
    __syncthreads();
    int nB = sNB < BND_CAP ? sNB : BND_CAP;
    for (int i = tid; i < BND_CAP; i += 1024) if (i >= nB) bnd[i] = 0ULL;
    __syncthreads();

    // bitonic sort bnd (desc), 2048 elems / 1024 threads
    for (int k = 2; k <= BND_CAP; k <<= 1) {
        for (int j = k >> 1; j > 0; j >>= 1) {
            #pragma unroll
            for (int h = 0; h < 2; h++) {
                int i = tid + h * 1024;
                int ixj = i ^ j;
                if (ixj > i) {
                    bool desc = ((i & k) == 0);
                    unsigned long long a = bnd[i], d = bnd[ixj];
                    bool sw = desc ? (a < d) : (a > d);
                    if (sw) { bnd[i] = d; bnd[ixj] = a; }
                }
            }
            __syncthreads();
        }
    }

    int nW = sNW;
    int need = TOPK - nW;
    for (int i = tid; i < need; i += 1024) win[nW + i] = bnd[i];
    __syncthreads();

    // final sort needed only when there are unsorted winners
    if (nW > 0) {
        for (int k = 2; k <= TOPK; k <<= 1) {
            for (int j = k >> 1; j > 0; j >>= 1) {
                int i = tid, ixj = i ^ j;
                if (ixj > i) {
                    bool desc = ((i & k) == 0);
                    unsigned long long a = win[i], d = win[ixj];
                    bool sw = desc ? (a < d) : (a > d);
                    if (sw) { win[i] = d; win[ixj] = a; }
                }
                __syncthreads();
            }
        }
    }

    // decode + emit
    {
        unsigned long long key = win[tid];
        unsigned u = (unsigned)(key >> 32);
        unsigned fb = (u & 0x80000000u) ? (u ^ 0x80000000u) : ~u;
        float score = __uint_as_float(fb);
        unsigned idx = ~((unsigned)(key & 0xffffffffu));

        const float* p = in + ((size_t)b * NN + idx) * STRIDE;
        float cx = p[0], cy = p[1], w = p[2], h = p[3];
        float x1 = cx - w * 0.5f, y1 = cy - h * 0.5f;
        float x2 = cx + w * 0.5f, y2 = cy + h * 0.5f;
        float cf = (float)g_cls[(size_t)b * NN + idx];
        float off = cf * MAX_WH;

        g_score [b * TOPK + tid] = score;
        g_box   [b * TOPK + tid] = make_float4(x1, y1, x2, y2);
        g_boxoff[b * TOPK + tid] = make_float4(x1 + off, y1 + off, x2 + off, y2 + off);
        g_clsf  [b * TOPK + tid] = cf;
    }
}

// =====================================================================
// Kernel C1: parallel suppression bitmatrix (upper triangle only).
// mask[b][i][w] bit k set iff j=64w+k > i and iou(i,j) > thr.
// grid (128, BB), block 256: warp per row i, ballots over columns,
// starting at the column step containing i (lower words stay 0).
// =====================================================================
__global__ void __launch_bounds__(256) iou_kernel() {
    int b = blockIdx.y;
    int tid = threadIdx.x, warp = tid >> 5, lane = tid & 31;
    __shared__ float4 cb[TOPK];
    for (int j = tid; j < TOPK; j += 256) cb[j] = g_boxoff[b * TOPK + j];
    __syncthreads();

    int i = blockIdx.x * 8 + warp;
    float4 bi = cb[i];
    float ai = (bi.z - bi.x) * (bi.w - bi.y);
    unsigned long long myw = 0;
    int s0 = i >> 5;                      // first step containing any j > i
    #pragma unroll 4
    for (int s = s0; s < 32; s++) {
        int j = s * 32 + lane;
        float4 bj = cb[j];
        float lx = fmaxf(bi.x, bj.x);
        float ly = fmaxf(bi.y, bj.y);
        float rx = fminf(bi.z, bj.z);
        float ry = fminf(bi.w, bj.w);
        float iw = fmaxf(rx - lx, 0.0f);
        float ih = fmaxf(ry - ly, 0.0f);
        float inter = iw * ih;
        float aj = (bj.z - bj.x) * (bj.w - bj.y);
        float iou = inter / (ai + aj - inter + 1e-07f);
        bool pred = (j > i) && (iou > IOU_THR);
        unsigned bal = __ballot_sync(0xffffffffu, pred);
        if (lane == (s >> 1)) myw |= ((unsigned long long)bal) << ((s & 1) * 32);
    }
    if (lane < 16) g_mask[((size_t)b * TOPK + i) * 16 + lane] = myw;
}

// =====================================================================
// Kernel C2: single-warp ffs-jump greedy sweep over full smem-cached
// mask (128KB dynamic smem) + stats + det[2] output + fused final
// reduction (last block). grid BB, block 512.
// =====================================================================
__global__ void __launch_bounds__(512) nms_kernel(float* __restrict__ out) {
    extern __shared__ unsigned long long sRows[];       // TOPK*16 words
    int b = blockIdx.x, tid = threadIdx.x, warp = tid >> 5, lane = tid & 31;
    __shared__ unsigned long long sRem[16];
    __shared__ int sKeptIdx[MAXDET];
    __shared__ int sN;
    __shared__ float sRed[16];

    const unsigned long long* mrow = g_mask + (size_t)b * TOPK * 16;
    #pragma unroll 8
    for (int k = tid; k < TOPK * 16; k += 512) sRows[k] = mrow[k];

    // init removed bitmap: 16 warps each build one 64-bit word via ballots
    {
        float s0 = g_score[b * TOPK + warp * 64 + lane];
        float s1 = g_score[b * TOPK + warp * 64 + 32 + lane];
        unsigned lo = __ballot_sync(0xffffffffu, s0 <= 0.0f);
        unsigned hi = __ballot_sync(0xffffffffu, s1 <= 0.0f);
        if (lane == 0) sRem[warp] = ((unsigned long long)hi << 32) | lo;
    }
    __syncthreads();

    if (warp == 0) {
        // lane l (l<16) owns word l; bit set = removed/processed
        unsigned long long rem = (lane < 16) ? sRem[lane] : ~0ULL;
        int kept = 0;
        for (;;) {
            unsigned long long inv = ~rem;
            unsigned cand = 0xFFFFFFFFu;
            if (inv) cand = (unsigned)(lane * 64 + __ffsll((long long)inv) - 1);
            unsigned i = __reduce_min_sync(0xffffffffu, cand);
            if (i >= TOPK) break;
            if (lane == 0) sKeptIdx[kept] = (int)i;
            kept++;
            if (kept >= MAXDET) break;
            unsigned long long r = (lane < 16) ? sRows[i * 16 + lane] : 0ULL;
            rem |= r;
            if (lane == (i >> 6)) rem |= 1ULL << (i & 63);
        }
        if (lane == 0) sN = kept;
    }
    __syncthreads();
    int n = sN;

    float contrib = 0.0f;
    float4 bbx = make_float4(0, 0, 0, 0);
    float sc = 0.0f, cf = 0.0f;
    bool emit = (tid < n);
    if (emit) {
        int i = sKeptIdx[tid];
        sc = g_score[b * TOPK + i];
        bbx = g_box[b * TOPK + i];
        cf = g_clsf[b * TOPK + i];
        contrib = (fabsf(bbx.x - bbx.z) + fabsf(bbx.y - bbx.w)) * sc;
    }

    // block sum (16 warps)
    float v = contrib;
    #pragma unroll
    for (int o = 16; o > 0; o >>= 1) v += __shfl_down_sync(0xffffffffu, v, o);
    if (lane == 0) sRed[warp] = v;
    __syncthreads();
    if (tid == 0) {
        float x = 0.0f;
        #pragma unroll
        for (int k = 0; k < 16; k++) x += sRed[k];
        int mx = n > 1 ? n : 1;
        g_bwh[b]  = (n > 0) ? (x / (2.0f * (float)mx)) : 0.0f;
        g_bmax[b] = (n > 0) ? g_score[b * TOPK + sKeptIdx[0]] : 0.0f;
    }

    // det[2] -> out[2 + r*6 ..]
    if (b == 2) {
        if (emit) {
            float* row = out + 2 + tid * 6;
            row[0] = bbx.x; row[1] = bbx.y; row[2] = bbx.z; row[3] = bbx.w;
            row[4] = sc; row[5] = cf;
        }
        if (tid >= n && tid < MAXDET) {
            float* row = out + 2 + tid * 6;
            #pragma unroll
            for (int k = 0; k < 6; k++) row[k] = 0.0f;
        }
    }

    // fused final reduction: last block to finish does the 16-wide sums
    __syncthreads();
    if (tid == 0) {
        __threadfence();
        if (atomicAdd(&g_ctr, 1) == BB - 1) {
            float m = 0.0f, w = 0.0f;
            #pragma unroll
            for (int k = 0; k < BB; k++) {
                m += __ldcg(&g_bmax[k]);
                w += __ldcg(&g_bwh[k]);
            }
            out[0] = m / (float)BB;
            out[1] = w / (float)BB;
        }
    }
}

extern "C" void kernel_launch(void* const* d_in, const int* in_sizes, int n_in,
                              void* d_out, int out_size) {
    const float* in = (const float*)d_in[0];
    float* out = (float*)d_out;

    // Allow 128KB dynamic smem for the full mask cache (host-side attribute,
    // runs once at capture; no allocation, no sync).
    static bool attr_done = false;
    if (!attr_done) {
        cudaFuncSetAttribute(nms_kernel,
                             cudaFuncAttributeMaxDynamicSharedMemorySize,
                             TOPK * 16 * (int)sizeof(unsigned long long));
        attr_done = true;
    }

    score_kernel<<<BB * NN / 16, 256>>>(in);   // 25200 blocks
    select_kernel<<<BB, 1024>>>(in);
    iou_kernel<<<dim3(TOPK / 8, BB), 256>>>();
    nms_kernel<<<BB, 512, TOPK * 16 * sizeof(unsigned long long)>>>(out);
}

// round 8
// speedup vs baseline: 1.2908x; 1.1774x over previous
#include <cuda_runtime.h>
#include <cstdint>

#define BB 16
#define NN 25200
#define NCLS 80
#define STRIDE 85
#define TOPK 1024
#define MAXDET 300
#define CONF_THRES 0.25f
#define IOU_THR 0.45f
#define MAX_WH 7680.0f
#define BND_CAP 2048

// -------- scratch (device globals, no allocations) --------
__device__ unsigned long long g_keys[BB * NN];
__device__ unsigned char     g_cls[BB * NN];
__device__ float  g_score [BB * TOPK];
__device__ float4 g_box   [BB * TOPK];   // un-offset xyxy
__device__ float4 g_boxoff[BB * TOPK];   // class-offset xyxy
__device__ float  g_clsf  [BB * TOPK];
__device__ unsigned long long g_mask[(size_t)BB * TOPK * 16]; // suppression bitmatrix
__device__ float  g_bmax[BB];
__device__ float  g_bwh [BB];
__device__ int    g_ctr;

// =====================================================================
// Kernel A: block of 256 stages 16 anchors (5440B) via aligned float4,
// then warp-per-anchor score/argmax from smem using REDUX.
// key = sortable(score)<<32 | ~anchor  (desc value, asc index ties)
// =====================================================================
__global__ void __launch_bounds__(256) score_kernel(const float* __restrict__ in) {
    __shared__ float s[16 * STRIDE];   // 1360 floats
    int group = blockIdx.x;
    int tid = threadIdx.x;
    if (group == 0 && tid == 0) g_ctr = 0;   // reset for fused final (stream-ordered)

    const float4* src = (const float4*)in + (size_t)group * 340;
    float4* dst = (float4*)s;
    {
        int k0 = tid, k1 = tid + 256;
        dst[k0] = src[k0];
        if (k1 < 340) dst[k1] = src[k1];
    }
    __syncthreads();

    int warp = tid >> 5, lane = tid & 31;
    #pragma unroll
    for (int a0 = 0; a0 < 2; a0++) {
        int a = warp + a0 * 8;
        const float* p = s + a * STRIDE;
        float obj = p[4];                       // broadcast LDS (uniform addr)

        float score = -1.0f;
        int cls = 0;
        if (obj > CONF_THRES) {                 // warp-uniform branch
            float v0 = p[lane];
            float v1 = p[lane + 32];
            float v2 = (lane < STRIDE - 64) ? p[lane + 64] : 0.0f;

            // per-lane best over its class elements (ascending class order)
            float best = -1.0f; int bidx = 1 << 24;
            if (lane >= 5) {
                float pr = v0 * obj;
                if (pr > best) { best = pr; bidx = lane - 5; }
            }
            {
                float pr = v1 * obj; int ci = lane + 27;
                if (pr > best) { best = pr; bidx = ci; }
            }
            if (lane < 21) {
                float pr = v2 * obj; int ci = lane + 59;
                if (pr > best) { best = pr; bidx = ci; }
            }
            // products are >= 0 so integer order == float order
            unsigned mybits = __float_as_uint(best);
            unsigned vmax = __reduce_max_sync(0xffffffffu, mybits);
            unsigned cand = (mybits == vmax) ? (unsigned)bidx : 0xFFFFFFFFu;
            unsigned cmin = __reduce_min_sync(0xffffffffu, cand);
            float conf = __uint_as_float(vmax);
            cls = (int)cmin;
            score = (conf > CONF_THRES) ? conf : -1.0f;
        }
        if (lane == 0) {
            int gidx = group * 16 + a;
            unsigned u = __float_as_uint(score);
            u = (u & 0x80000000u) ? ~u : (u | 0x80000000u);
            unsigned anchor = (unsigned)(gidx % NN);
            g_keys[gidx] = ((unsigned long long)u << 32) | (unsigned)(~anchor);
            g_cls[gidx] = (unsigned char)cls;
        }
    }
}

// =====================================================================
// Kernel B: per-batch exact sorted top-1024 via 12-bit radix select +
// bitonic sorts. 1 block (1024 thr) per batch. Warp-shuffle scan.
// =====================================================================
__global__ void __launch_bounds__(1024) select_kernel(const float* __restrict__ in) {
    int b = blockIdx.x;
    int tid = threadIdx.x;
    int warp = tid >> 5, lane = tid & 31;

    __shared__ unsigned hist[4096];
    __shared__ unsigned sWsum[32];
    __shared__ unsigned long long win[TOPK];
    __shared__ unsigned long long bnd[BND_CAP];
    __shared__ int sT, sNW, sNB;

    const unsigned long long* keys = g_keys + (size_t)b * NN;

    for (int i = tid; i < 4096; i += 1024) hist[i] = 0;
    __syncthreads();
    for (int i = tid; i < NN; i += 1024) {
        unsigned bin = (unsigned)(keys[i] >> 52);
        atomicAdd(&hist[bin], 1u);
    }
    __syncthreads();

    // descending-bin counts; thread t covers rbins 4t..4t+3
    unsigned cnt[4]; unsigned psum = 0;
    #pragma unroll
    for (int k = 0; k < 4; k++) { cnt[k] = hist[4095 - (4 * tid + k)]; psum += cnt[k]; }
    // warp-shuffle exclusive scan over 1024 threads
    unsigned inc = psum;
    #pragma unroll
    for (int o = 1; o < 32; o <<= 1) {
        unsigned t = __shfl_up_sync(0xffffffffu, inc, o);
        if (lane >= o) inc += t;
    }
    if (lane == 31) sWsum[warp] = inc;
    __syncthreads();
    if (warp == 0) {
        unsigned wv = sWsum[lane];
        unsigned wi = wv;
        #pragma unroll
        for (int o = 1; o < 32; o <<= 1) {
            unsigned t = __shfl_up_sync(0xffffffffu, wi, o);
            if (lane >= o) wi += t;
        }
        sWsum[lane] = wi - wv;  // exclusive warp offset
    }
    __syncthreads();
    unsigned before = sWsum[warp] + inc - psum;

    unsigned c = before;
    #pragma unroll
    for (int k = 0; k < 4; k++) {
        unsigned h = cnt[k];
        if (c < TOPK && c + h >= TOPK) sT = 4095 - (4 * tid + k);
        c += h;
    }
    if (tid == 0) { sNW = 0; sNB = 0; }
    __syncthreads();

    int T = sT;
    for (int i = tid; i < NN; i += 1024) {
        unsigned long long k = keys[i];
        int bin = (int)(k >> 52);
        if (bin > T) { int pos = atomicAdd(&sNW, 1); win[pos] = k; }
        else if (bin == T) { int pos = atomicAdd(&sNB, 1); if (pos < BND_CAP) bnd[pos] = k; }
    }
    __syncthreads();
    int nB = sNB < BND_CAP ? sNB : BND_CAP;
    for (int i = tid; i < BND_CAP; i += 1024) if (i >= nB) bnd[i] = 0ULL;
    __syncthreads();

    // bitonic sort bnd (desc), 2048 elems / 1024 threads
    for (int k = 2; k <= BND_CAP; k <<= 1) {
        for (int j = k >> 1; j > 0; j >>= 1) {
            #pragma unroll
            for (int h = 0; h < 2; h++) {
                int i = tid + h * 1024;
                int ixj = i ^ j;
                if (ixj > i) {
                    bool desc = ((i & k) == 0);
                    unsigned long long a = bnd[i], d = bnd[ixj];
                    bool sw = desc ? (a < d) : (a > d);
                    if (sw) { bnd[i] = d; bnd[ixj] = a; }
                }
            }
            __syncthreads();
        }
    }

    int nW = sNW;
    int need = TOPK - nW;
    for (int i = tid; i < need; i += 1024) win[nW + i] = bnd[i];
    __syncthreads();

    // final sort needed only when there are unsorted winners
    if (nW > 0) {
        for (int k = 2; k <= TOPK; k <<= 1) {
            for (int j = k >> 1; j > 0; j >>= 1) {
                int i = tid, ixj = i ^ j;
                if (ixj > i) {
                    bool desc = ((i & k) == 0);
                    unsigned long long a = win[i], d = win[ixj];
                    bool sw = desc ? (a < d) : (a > d);
                    if (sw) { win[i] = d; win[ixj] = a; }
                }
                __syncthreads();
            }
        }
    }

    // decode + emit
    {
        unsigned long long key = win[tid];
        unsigned u = (unsigned)(key >> 32);
        unsigned fb = (u & 0x80000000u) ? (u ^ 0x80000000u) : ~u;
        float score = __uint_as_float(fb);
        unsigned idx = ~((unsigned)(key & 0xffffffffu));

        const float* p = in + ((size_t)b * NN + idx) * STRIDE;
        float cx = p[0], cy = p[1], w = p[2], h = p[3];
        float x1 = cx - w * 0.5f, y1 = cy - h * 0.5f;
        float x2 = cx + w * 0.5f, y2 = cy + h * 0.5f;
        float cf = (float)g_cls[(size_t)b * NN + idx];
        float off = cf * MAX_WH;

        g_score [b * TOPK + tid] = score;
        g_box   [b * TOPK + tid] = make_float4(x1, y1, x2, y2);
        g_boxoff[b * TOPK + tid] = make_float4(x1 + off, y1 + off, x2 + off, y2 + off);
        g_clsf  [b * TOPK + tid] = cf;
    }
}

// =====================================================================
// Kernel C1: parallel suppression bitmatrix (upper triangle only).
// mask[b][i][w] bit k set iff j=64w+k > i and iou(i,j) > thr.
// =====================================================================
__global__ void __launch_bounds__(256) iou_kernel() {
    int b = blockIdx.y;
    int tid = threadIdx.x, warp = tid >> 5, lane = tid & 31;
    __shared__ float4 cb[TOPK];
    for (int j = tid; j < TOPK; j += 256) cb[j] = g_boxoff[b * TOPK + j];
    __syncthreads();

    int i = blockIdx.x * 8 + warp;
    float4 bi = cb[i];
    float ai = (bi.z - bi.x) * (bi.w - bi.y);
    unsigned long long myw = 0;
    int s0 = i >> 5;                      // first step containing any j > i
    #pragma unroll 4
    for (int s = s0; s < 32; s++) {
        int j = s * 32 + lane;
        float4 bj = cb[j];
        float lx = fmaxf(bi.x, bj.x);
        float ly = fmaxf(bi.y, bj.y);
        float rx = fminf(bi.z, bj.z);
        float ry = fminf(bi.w, bj.w);
        float iw = fmaxf(rx - lx, 0.0f);
        float ih = fmaxf(ry - ly, 0.0f);
        float inter = iw * ih;
        float aj = (bj.z - bj.x) * (bj.w - bj.y);
        float iou = inter / (ai + aj - inter + 1e-07f);
        bool pred = (j > i) && (iou > IOU_THR);
        unsigned bal = __ballot_sync(0xffffffffu, pred);
        if (lane == (s >> 1)) myw |= ((unsigned long long)bal) << ((s & 1) * 32);
    }
    if (lane < 16) g_mask[((size_t)b * TOPK + i) * 16 + lane] = myw;
}

// =====================================================================
// Kernel C2: broadcast-LDS greedy sweep (warp 0, no shuffles on the
// chain), full mask in 128KB dynamic smem, stats + det[2] + fused
// final reduction. grid BB, block 512.
// =====================================================================
__global__ void __launch_bounds__(512) nms_kernel(float* __restrict__ out) {
    extern __shared__ unsigned long long sRows[];       // TOPK*16 words
    int b = blockIdx.x, tid = threadIdx.x, warp = tid >> 5, lane = tid & 31;
    __shared__ unsigned long long sRem[16];
    __shared__ int sKeptIdx[MAXDET];
    __shared__ int sN;
    __shared__ float sRed[16];

    const unsigned long long* mrow = g_mask + (size_t)b * TOPK * 16;
    #pragma unroll 8
    for (int k = tid; k < TOPK * 16; k += 512) sRows[k] = mrow[k];

    // init removed bitmap: 16 warps each build one 64-bit word via ballots
    {
        float s0 = g_score[b * TOPK + warp * 64 + lane];
        float s1 = g_score[b * TOPK + warp * 64 + 32 + lane];
        unsigned lo = __ballot_sync(0xffffffffu, s0 <= 0.0f);
        unsigned hi = __ballot_sync(0xffffffffu, s1 <= 0.0f);
        if (lane == 0) sRem[warp] = ((unsigned long long)hi << 32) | lo;
    }
    __syncthreads();

    if (warp == 0) {
        // lane l (l<16) owns rem word l (future-word suppression accumulator)
        unsigned long long remw = (lane < 16) ? sRem[lane] : ~0ULL;
        int w = 0;
        // alive replicated identically in ALL lanes (word w, selectable bits)
        unsigned long long alive = ~__shfl_sync(0xffffffffu, remw, 0);
        int kept = 0;
        for (;;) {
            if (alive == 0) {                 // advance cursor (rare, uniform)
                w++;
                while (w < 16) {
                    unsigned long long t = __shfl_sync(0xffffffffu, remw, w);
                    if (t != ~0ULL) { alive = ~t; break; }
                    w++;
                }
                if (w >= 16) break;
                continue;
            }
            int bit = __ffsll((long long)alive) - 1;
            int i = w * 64 + bit;
            if (lane == 0) sKeptIdx[kept] = i;
            kept++;
            if (kept >= MAXDET) break;
            // chain: broadcast LDS of row word w; off-chain: lane word OR
            unsigned long long rcur = sRows[i * 16 + w];
            unsigned long long rown = (lane < 16) ? sRows[i * 16 + lane] : 0ULL;
            remw |= rown;
            alive = (alive & (alive - 1)) & ~rcur;
        }
        if (lane == 0) sN = kept;
    }
    __syncthreads();
    int n = sN;

    float contrib = 0.0f;
    float4 bbx = make_float4(0, 0, 0, 0);
    float sc = 0.0f, cf = 0.0f;
    bool emit = (tid < n);
    if (emit) {
        int i = sKeptIdx[tid];
        sc = g_score[b * TOPK + i];
        bbx = g_box[b * TOPK + i];
        cf = g_clsf[b * TOPK + i];
        contrib = (fabsf(bbx.x - bbx.z) + fabsf(bbx.y - bbx.w)) * sc;
    }

    // block sum (16 warps)
    float v = contrib;
    #pragma unroll
    for (int o = 16; o > 0; o >>= 1) v += __shfl_down_sync(0xffffffffu, v, o);
    if (lane == 0) sRed[warp] = v;
    __syncthreads();
    if (tid == 0) {
        float x = 0.0f;
        #pragma unroll
        for (int k = 0; k < 16; k++) x += sRed[k];
        int mx = n > 1 ? n : 1;
        g_bwh[b]  = (n > 0) ? (x / (2.0f * (float)mx)) : 0.0f;
        g_bmax[b] = (n > 0) ? g_score[b * TOPK + sKeptIdx[0]] : 0.0f;
    }

    // det[2] -> out[2 + r*6 ..]
    if (b == 2) {
        if (emit) {
            float* row = out + 2 + tid * 6;
            row[0] = bbx.x; row[1] = bbx.y; row[2] = bbx.z; row[3] = bbx.w;
            row[4] = sc; row[5] = cf;
        }
        if (tid >= n && tid < MAXDET) {
            float* row = out + 2 + tid * 6;
            #pragma unroll
            for (int k = 0; k < 6; k++) row[k] = 0.0f;
        }
    }

    // fused final reduction: last block to finish does the 16-wide sums
    __syncthreads();
    if (tid == 0) {
        __threadfence();
        if (atomicAdd(&g_ctr, 1) == BB - 1) {
            float m = 0.0f, w2 = 0.0f;
            #pragma unroll
            for (int k = 0; k < BB; k++) {
                m += __ldcg(&g_bmax[k]);
                w2 += __ldcg(&g_bwh[k]);
            }
            out[0] = m / (float)BB;
            out[1] = w2 / (float)BB;
        }
    }
}

extern "C" void kernel_launch(void* const* d_in, const int* in_sizes, int n_in,
                              void* d_out, int out_size) {
    const float* in = (const float*)d_in[0];
    float* out = (float*)d_out;

    static bool attr_done = false;
    if (!attr_done) {
        cudaFuncSetAttribute(nms_kernel,
                             cudaFuncAttributeMaxDynamicSharedMemorySize,
                             TOPK * 16 * (int)sizeof(unsigned long long));
        attr_done = true;
    }

    score_kernel<<<BB * NN / 16, 256>>>(in);   // 25200 blocks
    select_kernel<<<BB, 1024>>>(in);
    iou_kernel<<<dim3(TOPK / 8, BB), 256>>>();
    nms_kernel<<<BB, 512, TOPK * 16 * sizeof(unsigned long long)>>>(out);
}

// round 9
// speedup vs baseline: 1.3209x; 1.0233x over previous
#include <cuda_runtime.h>
#include <cstdint>

#define BB 16
#define NN 25200
#define NCLS 80
#define STRIDE 85
#define TOPK 1024
#define MAXDET 300
#define CONF_THRES 0.25f
#define IOU_THR 0.45f
#define MAX_WH 7680.0f
#define BND_CAP 2048

// -------- scratch (device globals, no allocations) --------
__device__ unsigned long long g_keys[BB * NN];
__device__ unsigned char     g_cls[BB * NN];
__device__ float  g_score [BB * TOPK];
__device__ float4 g_box   [BB * TOPK];   // un-offset xyxy
__device__ float4 g_boxoff[BB * TOPK];   // class-offset xyxy
__device__ float  g_clsf  [BB * TOPK];
__device__ unsigned long long g_mask[(size_t)BB * TOPK * 16]; // suppression bitmatrix
__device__ float  g_bmax[BB];
__device__ float  g_bwh [BB];
__device__ int    g_ctr;

// =====================================================================
// Kernel A: block of 256 stages 16 anchors (5440B) via aligned float4,
// then warp-per-anchor score/argmax from smem using REDUX.
// key = sortable(score)<<32 | ~anchor  (desc value, asc index ties)
// =====================================================================
__global__ void __launch_bounds__(256) score_kernel(const float* __restrict__ in) {
    __shared__ float s[16 * STRIDE];   // 1360 floats
    int group = blockIdx.x;
    int tid = threadIdx.x;
    if (group == 0 && tid == 0) g_ctr = 0;   // reset for fused final (stream-ordered)

    const float4* src = (const float4*)in + (size_t)group * 340;
    float4* dst = (float4*)s;
    {
        int k0 = tid, k1 = tid + 256;
        dst[k0] = src[k0];
        if (k1 < 340) dst[k1] = src[k1];
    }
    __syncthreads();

    int warp = tid >> 5, lane = tid & 31;
    #pragma unroll
    for (int a0 = 0; a0 < 2; a0++) {
        int a = warp + a0 * 8;
        const float* p = s + a * STRIDE;
        float obj = p[4];                       // broadcast LDS (uniform addr)

        float score = -1.0f;
        int cls = 0;
        if (obj > CONF_THRES) {                 // warp-uniform branch
            float v0 = p[lane];
            float v1 = p[lane + 32];
            float v2 = (lane < STRIDE - 64) ? p[lane + 64] : 0.0f;

            // per-lane best over its class elements (ascending class order)
            float best = -1.0f; int bidx = 1 << 24;
            if (lane >= 5) {
                float pr = v0 * obj;
                if (pr > best) { best = pr; bidx = lane - 5; }
            }
            {
                float pr = v1 * obj; int ci = lane + 27;
                if (pr > best) { best = pr; bidx = ci; }
            }
            if (lane < 21) {
                float pr = v2 * obj; int ci = lane + 59;
                if (pr > best) { best = pr; bidx = ci; }
            }
            // products are >= 0 so integer order == float order
            unsigned mybits = __float_as_uint(best);
            unsigned vmax = __reduce_max_sync(0xffffffffu, mybits);
            unsigned cand = (mybits == vmax) ? (unsigned)bidx : 0xFFFFFFFFu;
            unsigned cmin = __reduce_min_sync(0xffffffffu, cand);
            float conf = __uint_as_float(vmax);
            cls = (int)cmin;
            score = (conf > CONF_THRES) ? conf : -1.0f;
        }
        if (lane == 0) {
            int gidx = group * 16 + a;
            unsigned u = __float_as_uint(score);
            u = (u & 0x80000000u) ? ~u : (u | 0x80000000u);
            unsigned anchor = (unsigned)(gidx % NN);
            g_keys[gidx] = ((unsigned long long)u << 32) | (unsigned)(~anchor);
            g_cls[gidx] = (unsigned char)cls;
        }
    }
}

// =====================================================================
// Kernel B: per-batch exact sorted top-1024 via 12-bit radix select +
// bitonic sorts. 1 block (1024 thr) per batch. Warp-shuffle scan.
// =====================================================================
__global__ void __launch_bounds__(1024) select_kernel(const float* __restrict__ in) {
    int b = blockIdx.x;
    int tid = threadIdx.x;
    int warp = tid >> 5, lane = tid & 31;

    __shared__ unsigned hist[4096];
    __shared__ unsigned sWsum[32];
    __shared__ unsigned long long win[TOPK];
    __shared__ unsigned long long bnd[BND_CAP];
    __shared__ int sT, sNW, sNB;

    const unsigned long long* keys = g_keys + (size_t)b * NN;

    for (int i = tid; i < 4096; i += 1024) hist[i] = 0;
    __syncthreads();
    for (int i = tid; i < NN; i += 1024) {
        unsigned bin = (unsigned)(keys[i] >> 52);
        atomicAdd(&hist[bin], 1u);
    }
    __syncthreads();

    // descending-bin counts; thread t covers rbins 4t..4t+3
    unsigned cnt[4]; unsigned psum = 0;
    #pragma unroll
    for (int k = 0; k < 4; k++) { cnt[k] = hist[4095 - (4 * tid + k)]; psum += cnt[k]; }
    // warp-shuffle exclusive scan over 1024 threads
    unsigned inc = psum;
    #pragma unroll
    for (int o = 1; o < 32; o <<= 1) {
        unsigned t = __shfl_up_sync(0xffffffffu, inc, o);
        if (lane >= o) inc += t;
    }
    if (lane == 31) sWsum[warp] = inc;
    __syncthreads();
    if (warp == 0) {
        unsigned wv = sWsum[lane];
        unsigned wi = wv;
        #pragma unroll
        for (int o = 1; o < 32; o <<= 1) {
            unsigned t = __shfl_up_sync(0xffffffffu, wi, o);
            if (lane >= o) wi += t;
        }
        sWsum[lane] = wi - wv;  // exclusive warp offset
    }
    __syncthreads();
    unsigned before = sWsum[warp] + inc - psum;

    unsigned c = before;
    #pragma unroll
    for (int k = 0; k < 4; k++) {
        unsigned h = cnt[k];
        if (c < TOPK && c + h >= TOPK) sT = 4095 - (4 * tid + k);
        c += h;
    }
    if (tid == 0) { sNW = 0; sNB = 0; }
    __syncthreads();

    int T = sT;
    for (int i = tid; i < NN; i += 1024) {
        unsigned long long k = keys[i];
        int bin = (int)(k >> 52);
        if (bin > T) { int pos = atomicAdd(&sNW, 1); win[pos] = k; }
        else if (bin == T) { int pos = atomicAdd(&sNB, 1); if (pos < BND_CAP) bnd[pos] = k; }
    }
    __syncthreads();
    int nB = sNB < BND_CAP ? sNB : BND_CAP;
    for (int i = tid; i < BND_CAP; i += 1024) if (i >= nB) bnd[i] = 0ULL;
    __syncthreads();

    // bitonic sort bnd (desc), 2048 elems / 1024 threads
    for (int k = 2; k <= BND_CAP; k <<= 1) {
        for (int j = k >> 1; j > 0; j >>= 1) {
            #pragma unroll
            for (int h = 0; h < 2; h++) {
                int i = tid + h * 1024;
                int ixj = i ^ j;
                if (ixj > i) {
                    bool desc = ((i & k) == 0);
                    unsigned long long a = bnd[i], d = bnd[ixj];
                    bool sw = desc ? (a < d) : (a > d);
                    if (sw) { bnd[i] = d; bnd[ixj] = a; }
                }
            }
            __syncthreads();
        }
    }

    int nW = sNW;
    int need = TOPK - nW;
    for (int i = tid; i < need; i += 1024) win[nW + i] = bnd[i];
    __syncthreads();

    // final sort needed only when there are unsorted winners
    if (nW > 0) {
        for (int k = 2; k <= TOPK; k <<= 1) {
            for (int j = k >> 1; j > 0; j >>= 1) {
                int i = tid, ixj = i ^ j;
                if (ixj > i) {
                    bool desc = ((i & k) == 0);
                    unsigned long long a = win[i], d = win[ixj];
                    bool sw = desc ? (a < d) : (a > d);
                    if (sw) { win[i] = d; win[ixj] = a; }
                }
                __syncthreads();
            }
        }
    }

    // decode + emit
    {
        unsigned long long key = win[tid];
        unsigned u = (unsigned)(key >> 32);
        unsigned fb = (u & 0x80000000u) ? (u ^ 0x80000000u) : ~u;
        float score = __uint_as_float(fb);
        unsigned idx = ~((unsigned)(key & 0xffffffffu));

        const float* p = in + ((size_t)b * NN + idx) * STRIDE;
        float cx = p[0], cy = p[1], w = p[2], h = p[3];
        float x1 = cx - w * 0.5f, y1 = cy - h * 0.5f;
        float x2 = cx + w * 0.5f, y2 = cy + h * 0.5f;
        float cf = (float)g_cls[(size_t)b * NN + idx];
        float off = cf * MAX_WH;

        g_score [b * TOPK + tid] = score;
        g_box   [b * TOPK + tid] = make_float4(x1, y1, x2, y2);
        g_boxoff[b * TOPK + tid] = make_float4(x1 + off, y1 + off, x2 + off, y2 + off);
        g_clsf  [b * TOPK + tid] = cf;
    }
}

// =====================================================================
// Kernel C1: parallel suppression bitmatrix (upper triangle only).
// mask[b][i][w] bit k set iff j=64w+k > i and iou(i,j) > thr.
// =====================================================================
__global__ void __launch_bounds__(256) iou_kernel() {
    int b = blockIdx.y;
    int tid = threadIdx.x, warp = tid >> 5, lane = tid & 31;
    __shared__ float4 cb[TOPK];
    for (int j = tid; j < TOPK; j += 256) cb[j] = g_boxoff[b * TOPK + j];
    __syncthreads();

    int i = blockIdx.x * 8 + warp;
    float4 bi = cb[i];
    float ai = (bi.z - bi.x) * (bi.w - bi.y);
    unsigned long long myw = 0;
    int s0 = i >> 5;                      // first step containing any j > i
    #pragma unroll 4
    for (int s = s0; s < 32; s++) {
        int j = s * 32 + lane;
        float4 bj = cb[j];
        float lx = fmaxf(bi.x, bj.x);
        float ly = fmaxf(bi.y, bj.y);
        float rx = fminf(bi.z, bj.z);
        float ry = fminf(bi.w, bj.w);
        float iw = fmaxf(rx - lx, 0.0f);
        float ih = fmaxf(ry - ly, 0.0f);
        float inter = iw * ih;
        float aj = (bj.z - bj.x) * (bj.w - bj.y);
        float iou = inter / (ai + aj - inter + 1e-07f);
        bool pred = (j > i) && (iou > IOU_THR);
        unsigned bal = __ballot_sync(0xffffffffu, pred);
        if (lane == (s >> 1)) myw |= ((unsigned long long)bal) << ((s & 1) * 32);
    }
    if (lane < 16) g_mask[((size_t)b * TOPK + i) * 16 + lane] = myw;
}

// =====================================================================
// Kernel C2: word-major branch-lean greedy sweep (warp 0), full mask
// in 128KB dynamic smem (LDG.128 bulk load), stats + det[2] + fused
// final reduction. grid BB, block 512.
// =====================================================================
__global__ void __launch_bounds__(512) nms_kernel(float* __restrict__ out) {
    extern __shared__ unsigned long long sRows[];       // TOPK*16 words
    int b = blockIdx.x, tid = threadIdx.x, warp = tid >> 5, lane = tid & 31;
    __shared__ unsigned long long sRem[16];
    __shared__ int sKeptIdx[MAXDET];
    __shared__ int sN;
    __shared__ float sRed[16];

    // vectorized bulk load: 8192 x 16B
    {
        const ulonglong2* srcv = (const ulonglong2*)(g_mask + (size_t)b * TOPK * 16);
        ulonglong2* dstv = (ulonglong2*)sRows;
        #pragma unroll
        for (int k = 0; k < 16; k++)
            dstv[tid + k * 512] = srcv[tid + k * 512];
    }

    // init removed bitmap: 16 warps each build one 64-bit word via ballots
    {
        float s0 = g_score[b * TOPK + warp * 64 + lane];
        float s1 = g_score[b * TOPK + warp * 64 + 32 + lane];
        unsigned lo = __ballot_sync(0xffffffffu, s0 <= 0.0f);
        unsigned hi = __ballot_sync(0xffffffffu, s1 <= 0.0f);
        if (lane == 0) sRem[warp] = ((unsigned long long)hi << 32) | lo;
    }
    __syncthreads();

    if (warp == 0) {
        // lane l (l<16) owns rem word l (future-word suppression accumulator)
        unsigned long long remw = (lane < 16) ? sRem[lane] : ~0ULL;
        int kept = 0;
        for (int w = 0; w < 16; w++) {
            // alive bits of word w, replicated identically in all lanes
            unsigned long long alive = ~__shfl_sync(0xffffffffu, remw, w);
            while (alive) {
                int bit = __ffsll((long long)alive) - 1;
                int i = (w << 6) + bit;
                if (lane == 0) sKeptIdx[kept] = i;     // predicated STS
                kept++;
                if (kept >= MAXDET) goto sweep_done;   // rare forward branch
                unsigned long long rcur = sRows[i * 16 + w];          // broadcast
                unsigned long long rown = (lane < 16) ? sRows[i * 16 + lane] : 0ULL;
                remw |= rown;                           // off-chain
                alive = (alive & (alive - 1)) & ~rcur;  // chain: clear bit + suppressed
            }
        }
    sweep_done:
        if (lane == 0) sN = kept;
    }
    __syncthreads();
    int n = sN;

    float contrib = 0.0f;
    float4 bbx = make_float4(0, 0, 0, 0);
    float sc = 0.0f, cf = 0.0f;
    bool emit = (tid < n);
    if (emit) {
        int i = sKeptIdx[tid];
        sc = g_score[b * TOPK + i];
        bbx = g_box[b * TOPK + i];
        cf = g_clsf[b * TOPK + i];
        contrib = (fabsf(bbx.x - bbx.z) + fabsf(bbx.y - bbx.w)) * sc;
    }

    // block sum (16 warps)
    float v = contrib;
    #pragma unroll
    for (int o = 16; o > 0; o >>= 1) v += __shfl_down_sync(0xffffffffu, v, o);
    if (lane == 0) sRed[warp] = v;
    __syncthreads();
    if (tid == 0) {
        float x = 0.0f;
        #pragma unroll
        for (int k = 0; k < 16; k++) x += sRed[k];
        int mx = n > 1 ? n : 1;
        g_bwh[b]  = (n > 0) ? (x / (2.0f * (float)mx)) : 0.0f;
        g_bmax[b] = (n > 0) ? g_score[b * TOPK + sKeptIdx[0]] : 0.0f;
    }

    // det[2] -> out[2 + r*6 ..]
    if (b == 2) {
        if (emit) {
            float* row = out + 2 + tid * 6;
            row[0] = bbx.x; row[1] = bbx.y; row[2] = bbx.z; row[3] = bbx.w;
            row[4] = sc; row[5] = cf;
        }
        if (tid >= n && tid < MAXDET) {
            float* row = out + 2 + tid * 6;
            #pragma unroll
            for (int k = 0; k < 6; k++) row[k] = 0.0f;
        }
    }

    // fused final reduction: last block to finish does the 16-wide sums
    __syncthreads();
    if (tid == 0) {
        __threadfence();
        if (atomicAdd(&g_ctr, 1) == BB - 1) {
            float m = 0.0f, w2 = 0.0f;
            #pragma unroll
            for (int k = 0; k < BB; k++) {
                m += __ldcg(&g_bmax[k]);
                w2 += __ldcg(&g_bwh[k]);
            }
            out[0] = m / (float)BB;
            out[1] = w2 / (float)BB;
        }
    }
}

extern "C" void kernel_launch(void* const* d_in, const int* in_sizes, int n_in,
                              void* d_out, int out_size) {
    const float* in = (const float*)d_in[0];
    float* out = (float*)d_out;

    static bool attr_done = false;
    if (!attr_done) {
        cudaFuncSetAttribute(nms_kernel,
                             cudaFuncAttributeMaxDynamicSharedMemorySize,
                             TOPK * 16 * (int)sizeof(unsigned long long));
        attr_done = true;
    }

    score_kernel<<<BB * NN / 16, 256>>>(in);   // 25200 blocks
    select_kernel<<<BB, 1024>>>(in);
    iou_kernel<<<dim3(TOPK / 8, BB), 256>>>();
    nms_kernel<<<BB, 512, TOPK * 16 * sizeof(unsigned long long)>>>(out);
}